// round 6
// baseline (speedup 1.0000x reference)
#include <cuda_runtime.h>
#include <math.h>

// Problem constants (fixed by the benchmark shapes)
#define Bn 256
#define Tn 1024
#define Cn 256          // classes, blank = Cn-1
#define Ln 128
#define EDEAD (-(1 << 28))
#define NCH 4           // ring chunks per element
#define CF 8            // frames per chunk
#define RING_F (NCH * CF * Cn)   // floats per element ring = 8192

// exact 2^d for d in [-126, 0]; 0.0f below (relative flush)
__device__ __forceinline__ float p2f(int d) {
    return (d > -127) ? __int_as_float((127 + d) << 23) : 0.0f;
}
__device__ __forceinline__ void bar_arrive64(int id) {
    asm volatile("bar.arrive %0, 64;" :: "r"(id) : "memory");
}
__device__ __forceinline__ void bar_wait64(int id) {
    asm volatile("bar.sync %0, 64;" :: "r"(id) : "memory");
}

// Per-element recurrence state: lane owns states 8l..8l+7 as octet block-float
// (8 mantissas + shared exponent); state 256 carried redundantly on all lanes.
struct Ctc {
    float m0, m1, m2, m3, m4, m5, m6, m7;
    int   E;
    float m9; int e9;
    float k1, k3, k5, k7;
    int   c0, c1, c2, c3;
};

__device__ __forceinline__ void ctc_step(Ctc& S, const float* __restrict__ base,
                                         int OFF, int lane)
{
    float pb = base[(Cn - 1) + OFF];
    float q0 = base[S.c0 + OFF], q1 = base[S.c1 + OFF];
    float q2 = base[S.c2 + OFF], q3 = base[S.c3 + OFF];
    float om7 = S.m7; int oE = S.E;
    float pm7 = __shfl_up_sync(0xffffffffu, S.m7, 1);
    int   pE  = __shfl_up_sync(0xffffffffu, S.E,  1);
    if (lane == 0) pE = EDEAD;
    int emax = max(S.E, pE);
    int d    = emax - S.E;
    float scq = p2f(-d);
    float scp = p2f(pE - emax);
    float x0 = S.m0 * scq, x1 = S.m1 * scq, y7 = pm7 * scp;
    float n0 = x0 + y7;
    float n1 = fmaf(S.k1, y7, x0) + x1;
    float u2 = S.m2 + S.m1;
    float u3 = fmaf(S.k3, S.m1, S.m2) + S.m3;
    float u4 = S.m4 + S.m3;
    float u5 = fmaf(S.k5, S.m3, S.m4) + S.m5;
    float u6 = S.m6 + S.m5;
    float u7 = fmaf(S.k7, S.m5, S.m6) + S.m7;
    float w0 = pb * n0, w1 = q0 * n1;
    float w2 = pb * u2, w3 = q1 * u3;
    float w4 = pb * u4, w5 = q2 * u5;
    float w6 = pb * u6, w7 = q3 * u7;
    float mA = fmaxf(fmaxf(fmaxf(w2, w3), fmaxf(w4, w5)), fmaxf(w6, w7));
    float mx = fmaxf(fmaxf(w0, w1), mA * scq);
    int ef = __float_as_int(mx) >> 23;
    float sB = __int_as_float((254 - ef) << 23);
    float sA = p2f(127 - ef - d);
    S.E = emax + ef - 127;
    S.m0 = w0 * sB; S.m1 = w1 * sB;
    S.m2 = w2 * sA; S.m3 = w3 * sA; S.m4 = w4 * sA;
    S.m5 = w5 * sA; S.m6 = w6 * sA; S.m7 = w7 * sA;
    // state 256 (final blank): alpha' = pb * (a256 + a255_old)
    int em9 = max(S.e9, oE);
    float s9 = fmaf(S.m9, p2f(S.e9 - em9), om7 * p2f(oE - em9));
    float v9 = pb * s9;
    int ef9 = __float_as_int(v9) >> 23;
    S.e9 = em9 + ef9 - 127;
    S.m9 = v9 * __int_as_float((254 - ef9) << 23);
}

__device__ __forceinline__ void ctc_init(Ctc& S, const int* __restrict__ lab,
                                         const float* __restrict__ row, int lane)
{
    S.c0 = __ldg(lab + 4 * lane + 0);
    S.c1 = __ldg(lab + 4 * lane + 1);
    S.c2 = __ldg(lab + 4 * lane + 2);
    S.c3 = __ldg(lab + 4 * lane + 3);
    int cm1 = __shfl_up_sync(0xffffffffu, S.c3, 1);
    S.k1 = (lane > 0 && S.c0 != cm1) ? 1.0f : 0.0f;
    S.k3 = (S.c1 != S.c0) ? 1.0f : 0.0f;
    S.k5 = (S.c2 != S.c1) ? 1.0f : 0.0f;
    S.k7 = (S.c3 != S.c2) ? 1.0f : 0.0f;
    S.m0 = S.m1 = S.m2 = S.m3 = S.m4 = S.m5 = S.m6 = S.m7 = 0.0f;
    S.E = EDEAD; S.m9 = 0.0f; S.e9 = EDEAD;
    float v0 = __ldg(row + (Cn - 1)) + 1e-7f;
    float v1 = __ldg(row + S.c0) + 1e-7f;
    float mx = fmaxf(v0, v1);
    int ef = __float_as_int(mx) >> 23;
    float scr = __int_as_float((254 - ef) << 23);
    if (lane == 0) { S.E = ef - 127; S.m0 = v0 * scr; S.m1 = v1 * scr; }
}

__global__ void __launch_bounds__(96, 1)
ctc_dual_kernel(const int* __restrict__ labels,
                const float* __restrict__ ypred,
                float* __restrict__ out)
{
    extern __shared__ float ring[];                 // 2 * 8192 floats (64KB)
    const int lane = threadIdx.x & 31;
    const int warp = threadIdx.x >> 5;

    if (warp >= 1) {
        // ---------------- LOADER: stream frames into the smem ring ----------
        const int p = warp - 1;
        const int b = blockIdx.x * 2 + p;
        const float4* __restrict__ src =
            (const float4*)(ypred + (size_t)b * (size_t)(Tn * Cn));
        float* rp = ring + p * RING_F;
        float4 ca[CF], cb[CF];
        #pragma unroll
        for (int f = 0; f < CF; ++f) {
            ca[f] = __ldg(src + f * 64 + lane);
            cb[f] = __ldg(src + f * 64 + 32 + lane);
        }
        #pragma unroll 1
        for (int ck = 0; ck < Tn / CF; ++ck) {
            float4 na[CF], nb[CF];
            int nk = (ck + 1 < Tn / CF) ? ck + 1 : ck;
            #pragma unroll
            for (int f = 0; f < CF; ++f) {
                na[f] = __ldg(src + nk * 512 + f * 64 + lane);
                nb[f] = __ldg(src + nk * 512 + f * 64 + 32 + lane);
            }
            int slot = ck & (NCH - 1);
            if (ck >= NCH) bar_wait64(p * 8 + 4 + slot);  // slot freed?
            float4* dst = (float4*)(rp + slot * (CF * Cn));
            #pragma unroll
            for (int f = 0; f < CF; ++f) {
                float4 a = ca[f], bb = cb[f];
                a.x += 1e-7f; a.y += 1e-7f; a.z += 1e-7f; a.w += 1e-7f;
                bb.x += 1e-7f; bb.y += 1e-7f; bb.z += 1e-7f; bb.w += 1e-7f;
                dst[f * 64 + lane] = a;
                dst[f * 64 + 32 + lane] = bb;
            }
            bar_arrive64(p * 8 + slot);                   // slot filled
            #pragma unroll
            for (int f = 0; f < CF; ++f) { ca[f] = na[f]; cb[f] = nb[f]; }
        }
        return;
    }

    // -------- COMPUTE: one warp advances BOTH batch elements (2 chains) -----
    const int bA = blockIdx.x * 2 + 0;
    const int bB = blockIdx.x * 2 + 1;
    Ctc SA, SB;
    ctc_init(SA, labels + bA * Ln, ypred + (size_t)bA * (size_t)(Tn * Cn), lane);
    ctc_init(SB, labels + bB * Ln, ypred + (size_t)bB * (size_t)(Tn * Cn), lane);

    // Chunk 0: frames 1..7
    {
        bar_wait64(0); bar_wait64(8);
        const float* baA = ring;                     // elem A, slot 0
        const float* baB = ring + RING_F;            // elem B, slot 0
        #pragma unroll
        for (int f = 1; f < CF; ++f) {
            ctc_step(SA, baA, f * Cn, lane);
            ctc_step(SB, baB, f * Cn, lane);
        }
        bar_arrive64(4); bar_arrive64(12);
    }
    // Chunks 1..127: 8 frames each
    #pragma unroll 1
    for (int ck = 1; ck < Tn / CF; ++ck) {
        int slot = ck & (NCH - 1);
        bar_wait64(slot); bar_wait64(8 + slot);
        const float* baA = ring + slot * (CF * Cn);
        const float* baB = ring + RING_F + slot * (CF * Cn);
        #pragma unroll
        for (int f = 0; f < CF; ++f) {
            ctc_step(SA, baA, f * Cn, lane);
            ctc_step(SB, baB, f * Cn, lane);
        }
        bar_arrive64(4 + slot); bar_arrive64(12 + slot);
    }

    // loss = -log(alpha[255] + alpha[256]); both live on lane 31
    if (lane == 31) {
        int emA = max(SA.E, SA.e9);
        float tA = fmaf(SA.m7, p2f(SA.E - emA), SA.m9 * p2f(SA.e9 - emA));
        out[bA] = -(logf(tA) + (float)emA * 0.69314718055994530942f);
        int emB = max(SB.E, SB.e9);
        float tB = fmaf(SB.m7, p2f(SB.E - emB), SB.m9 * p2f(SB.e9 - emB));
        out[bB] = -(logf(tB) + (float)emB * 0.69314718055994530942f);
    }
}

extern "C" void kernel_launch(void* const* d_in, const int* in_sizes, int n_in,
                              void* d_out, int out_size)
{
    const int*   labels;
    const float* ypred;
    if (in_sizes[0] == Bn * Ln) {
        labels = (const int*)d_in[0];
        ypred  = (const float*)d_in[1];
    } else {
        labels = (const int*)d_in[1];
        ypred  = (const float*)d_in[0];
    }
    const int smem = 2 * RING_F * (int)sizeof(float);   // 64 KB
    cudaFuncSetAttribute(ctc_dual_kernel,
                         cudaFuncAttributeMaxDynamicSharedMemorySize, smem);
    ctc_dual_kernel<<<Bn / 2, 96, smem>>>(labels, ypred, (float*)d_out);
}

// round 7
// speedup vs baseline: 3.2858x; 3.2858x over previous
#include <cuda_runtime.h>
#include <math.h>
#include <stdint.h>

// Problem constants (fixed by the benchmark shapes)
#define Bn 256
#define Tn 1024
#define Cn 256          // classes, blank = Cn-1
#define Ln 128
#define EDEAD (-(1 << 28))
#define NCH 4           // ring chunks per element
#define CF 8            // frames per chunk
#define CHUNK_F (CF * Cn)          // 2048 floats
#define CHUNK_BYTES (CHUNK_F * 4)  // 8192 bytes
#define RING_F (NCH * CHUNK_F)     // 8192 floats per element

struct SmemLayout {
    float ring[2][RING_F];                 // 64 KB
    unsigned long long mbar[2][NCH];       // full barriers, one per slot
};

__device__ __forceinline__ uint32_t s2u(const void* p) {
    return (uint32_t)__cvta_generic_to_shared(p);
}
// exact 2^x; clamps: x <= -127 -> 0.0f, x >= 127 -> 2^127
__device__ __forceinline__ float e2f(int x) {
    x = max(-127, min(127, x));
    return __int_as_float((127 + x) << 23);
}
__device__ __forceinline__ void mbar_init(uint32_t a, uint32_t cnt) {
    asm volatile("mbarrier.init.shared.b64 [%0], %1;" :: "r"(a), "r"(cnt) : "memory");
}
__device__ __forceinline__ void mbar_expect(uint32_t a, uint32_t tx) {
    asm volatile("mbarrier.arrive.expect_tx.shared.b64 _, [%0], %1;"
                 :: "r"(a), "r"(tx) : "memory");
}
__device__ __forceinline__ void bulk_g2s(uint32_t dst, const void* src,
                                         uint32_t bytes, uint32_t mbar) {
    asm volatile("cp.async.bulk.shared::cta.global.mbarrier::complete_tx::bytes "
                 "[%0], [%1], %2, [%3];"
                 :: "r"(dst), "l"(src), "r"(bytes), "r"(mbar) : "memory");
}
__device__ __forceinline__ void mbar_wait(uint32_t a, uint32_t parity) {
    uint32_t done;
    asm volatile("{\n\t.reg .pred p;\n\t"
                 "mbarrier.try_wait.parity.acquire.cta.shared::cta.b64 p, [%1], %2;\n\t"
                 "selp.b32 %0, 1, 0, p;\n\t}"
                 : "=r"(done) : "r"(a), "r"(parity) : "memory");
    if (!done) {
        asm volatile("{\n\t.reg .pred P1;\n\t"
                     "WL%=:\n\t"
                     "mbarrier.try_wait.parity.acquire.cta.shared::cta.b64 P1, [%0], %1;\n\t"
                     "@P1 bra WD%=;\n\t"
                     "bra WL%=;\n\t"
                     "WD%=:\n\t}"
                     :: "r"(a), "r"(parity) : "memory");
    }
}

// Per-element recurrence state: lane owns states 8l..8l+7 as octet block-float
// (8 mantissas + shared exponent E); state 256 carried per-lane (lane 31 valid).
struct Ctc {
    float m0, m1, m2, m3, m4, m5, m6, m7;
    int   E;
    float m9; int e9;
    float k1, k3, k5, k7;
    int   c0, c1, c2, c3;
};

// Run NS forward steps (frames f0..f0+NS-1 of chunk `base`) with exponents
// frozen for the whole group; renormalize once at group end.
template <int NS>
__device__ __forceinline__ void ctc_group(Ctc& S, const float* __restrict__ base,
                                          int f0, int lane)
{
    // ---- group prologue: establish frozen base & cross-lane scales ----
    int pE = __shfl_up_sync(0xffffffffu, S.E, 1);
    if (lane == 0) pE = EDEAD;
    int bse  = max(S.E, pE);
    int pbse = __shfl_up_sync(0xffffffffu, bse, 1);
    int k = pbse - bse;                // adjacent-octet base delta (can be > 0)
    if (lane == 0) k = -100000;        // no predecessor
    k = min(k, 254);
    int ka = k / 2, kb = k - ka;       // two exact factors cover |k| <= 254
    float dsc1 = e2f(ka), dsc2 = e2f(kb);
    float scq  = e2f(S.E - bse);       // align own mantissas (usually 1.0)
    S.m0 *= scq; S.m1 *= scq; S.m2 *= scq; S.m3 *= scq;
    S.m4 *= scq; S.m5 *= scq; S.m6 *= scq; S.m7 *= scq;
    S.E = bse;
    int b9 = max(S.e9, bse);           // state-256 scales (lane-local)
    S.m9 *= e2f(S.e9 - b9);
    S.e9 = b9;
    float sp9 = e2f(bse - b9);

    // ---- NS cheap steps (no exponent math on the recurrent path) ----
    #pragma unroll
    for (int f = 0; f < NS; ++f) {
        const float* fr = base + (f0 + f) * Cn;
        float pb = fr[Cn - 1] + 1e-7f;
        float q0 = fr[S.c0] + 1e-7f, q1 = fr[S.c1] + 1e-7f;
        float q2 = fr[S.c2] + 1e-7f, q3 = fr[S.c3] + 1e-7f;
        float om7 = S.m7;
        float pm7 = __shfl_up_sync(0xffffffffu, S.m7, 1);
        float y7 = (pm7 * dsc1) * dsc2;
        float n0 = S.m0 + y7;
        float n1 = fmaf(S.k1, y7, S.m0) + S.m1;
        float u2 = S.m2 + S.m1;
        float u3 = fmaf(S.k3, S.m1, S.m2) + S.m3;
        float u4 = S.m4 + S.m3;
        float u5 = fmaf(S.k5, S.m3, S.m4) + S.m5;
        float u6 = S.m6 + S.m5;
        float u7 = fmaf(S.k7, S.m5, S.m6) + S.m7;
        S.m0 = pb * n0; S.m1 = q0 * n1;
        S.m2 = pb * u2; S.m3 = q1 * u3;
        S.m4 = pb * u4; S.m5 = q2 * u5;
        S.m6 = pb * u6; S.m7 = q3 * u7;
        S.m9 = pb * fmaf(om7, sp9, S.m9);   // state 256: pb*(a256 + a255_old)
    }

    // ---- group epilogue: renormalize octet (and state 256) ----
    float mx = fmaxf(fmaxf(fmaxf(S.m0, S.m1), fmaxf(S.m2, S.m3)),
                     fmaxf(fmaxf(S.m4, S.m5), fmaxf(S.m6, S.m7)));
    int ef = (__float_as_int(mx) >> 23) & 0xFF;
    float scr = __int_as_float((254 - ef) << 23);   // exact 2^(127-ef)
    S.E += ef - 127;
    S.m0 *= scr; S.m1 *= scr; S.m2 *= scr; S.m3 *= scr;
    S.m4 *= scr; S.m5 *= scr; S.m6 *= scr; S.m7 *= scr;
    int ef9 = (__float_as_int(S.m9) >> 23) & 0xFF;
    S.e9 += ef9 - 127;
    S.m9 *= __int_as_float((254 - ef9) << 23);
}

__global__ void __launch_bounds__(64, 1)
ctc_tma_kernel(const int* __restrict__ labels,
               const float* __restrict__ ypred,
               float* __restrict__ out)
{
    extern __shared__ char smraw[];
    SmemLayout* sm = (SmemLayout*)smraw;
    const int lane = threadIdx.x & 31;
    const int warp = threadIdx.x >> 5;
    const int b = blockIdx.x * 2 + warp;             // one element per warp
    const float* __restrict__ row = ypred + (size_t)b * (size_t)(Tn * Cn);
    float* ring = sm->ring[warp];
    const uint32_t mb0 = s2u(&sm->mbar[warp][0]);

    // mbarrier init + async-proxy fence (per-warp; rings/mbars are private)
    if (lane == 0) {
        #pragma unroll
        for (int s = 0; s < NCH; ++s) mbar_init(mb0 + 8 * s, 1);
    }
    asm volatile("fence.proxy.async.shared::cta;" ::: "memory");
    __syncwarp();

    // prologue: issue bulk copies for chunks 0..3
    if (lane == 0) {
        #pragma unroll
        for (int s = 0; s < NCH; ++s) {
            mbar_expect(mb0 + 8 * s, CHUNK_BYTES);
            bulk_g2s(s2u(ring + s * CHUNK_F), row + s * CHUNK_F,
                     CHUNK_BYTES, mb0 + 8 * s);
        }
    }

    // ---- per-element CTC state init ----
    Ctc S;
    const int* __restrict__ lab = labels + b * Ln;
    S.c0 = __ldg(lab + 4 * lane + 0);
    S.c1 = __ldg(lab + 4 * lane + 1);
    S.c2 = __ldg(lab + 4 * lane + 2);
    S.c3 = __ldg(lab + 4 * lane + 3);
    int cm1 = __shfl_up_sync(0xffffffffu, S.c3, 1);
    S.k1 = (lane > 0 && S.c0 != cm1) ? 1.0f : 0.0f;
    S.k3 = (S.c1 != S.c0) ? 1.0f : 0.0f;
    S.k5 = (S.c2 != S.c1) ? 1.0f : 0.0f;
    S.k7 = (S.c3 != S.c2) ? 1.0f : 0.0f;
    S.m0 = S.m1 = S.m2 = S.m3 = S.m4 = S.m5 = S.m6 = S.m7 = 0.0f;
    S.E = EDEAD; S.m9 = 0.0f; S.e9 = EDEAD;
    {   // t=0: states 0 (blank) and 1 (label 0) live on lane 0
        float v0 = __ldg(row + (Cn - 1)) + 1e-7f;
        float v1 = __ldg(row + S.c0) + 1e-7f;
        float mx = fmaxf(v0, v1);
        int ef = (__float_as_int(mx) >> 23) & 0xFF;
        float scr = __int_as_float((254 - ef) << 23);
        if (lane == 0) { S.E = ef - 127; S.m0 = v0 * scr; S.m1 = v1 * scr; }
    }

    // ---- main loop: self-paced 4-slot ring, 8 frames per chunk ----
    #pragma unroll 1
    for (int ck = 0; ck < Tn / CF; ++ck) {
        int slot = ck & (NCH - 1);
        mbar_wait(mb0 + 8 * slot, (ck >> 2) & 1);
        const float* base = ring + slot * CHUNK_F;
        if (ck == 0) {              // frame 0 consumed by init; 7 steps
            ctc_group<4>(S, base, 1, lane);
            ctc_group<3>(S, base, 5, lane);
        } else {
            ctc_group<4>(S, base, 0, lane);
            ctc_group<4>(S, base, 4, lane);
        }
        // refill this slot with chunk ck+4 (same warp => program-order safe;
        // TMA data lands >>100 cycles after the last LDS of this chunk)
        int nk = ck + NCH;
        if (nk < Tn / CF && lane == 0) {
            mbar_expect(mb0 + 8 * slot, CHUNK_BYTES);
            bulk_g2s(s2u(ring + slot * CHUNK_F), row + nk * CHUNK_F,
                     CHUNK_BYTES, mb0 + 8 * slot);
        }
    }

    // loss = -log(alpha[255] + alpha[256]); both live on lane 31
    if (lane == 31) {
        int em = max(S.E, S.e9);
        float tot = fmaf(S.m7, e2f(S.E - em), S.m9 * e2f(S.e9 - em));
        out[b] = -(logf(tot) + (float)em * 0.69314718055994530942f);
    }
}

extern "C" void kernel_launch(void* const* d_in, const int* in_sizes, int n_in,
                              void* d_out, int out_size)
{
    const int*   labels;
    const float* ypred;
    if (in_sizes[0] == Bn * Ln) {
        labels = (const int*)d_in[0];
        ypred  = (const float*)d_in[1];
    } else {
        labels = (const int*)d_in[1];
        ypred  = (const float*)d_in[0];
    }
    const int smem = (int)sizeof(SmemLayout);      // ~64 KB + mbars
    cudaFuncSetAttribute(ctc_tma_kernel,
                         cudaFuncAttributeMaxDynamicSharedMemorySize, smem);
    ctc_tma_kernel<<<Bn / 2, 64, smem>>>(labels, ypred, (float*)d_out);
}